// round 6
// baseline (speedup 1.0000x reference)
#include <cuda_runtime.h>
#include <cuda_bf16.h>
#include <math.h>

// Problem constants (fixed by the reference)
#define NN 100000
#define EE 1600000
#define FIN 32
#define HH 16
#define CC 10

// ---------------- scratch (no allocation allowed -> __device__ globals) ----------------
// P1[n][0..15]  = (x @ W0)[n]      (A)
// P1[n][16..31] = (x @ (W1-W0))[n] (B)
__device__ __align__(16) float g_P1[NN * 32];       // 12.8 MB
__device__ __align__(16) float g_R1[NN * 16];       //  6.4 MB  x @ root1
__device__ __align__(16) float g_agg1[NN * 16];     //  6.4 MB
__device__ __align__(16) float g_deg[NN];           //  0.4 MB
// P2[n][0..11]  = (h @ W0_2) padded 10->12, P2[n][12..23] = (h @ (W1_2-W0_2)) padded
__device__ __align__(16) float g_P2[NN * 24];       //  9.6 MB
__device__ __align__(16) float g_R2[NN * 12];       //  4.8 MB  h @ root2 padded 10->12
__device__ __align__(16) float g_agg2[NN * 12];     //  4.8 MB

// Vector reduction helper: use the CUDA >=12.8 float4 atomicAdd intrinsic
// (lowers to RED.ADD.F32x4 on sm_90+); scalar fallback otherwise.
__device__ __forceinline__ void red_add_f4(float* d, float4 m) {
#if defined(__CUDA_ARCH__) && (__CUDA_ARCH__ >= 900) && (CUDART_VERSION >= 12080)
    atomicAdd(reinterpret_cast<float4*>(d), m);
#else
    atomicAdd(d + 0, m.x);
    atomicAdd(d + 1, m.y);
    atomicAdd(d + 2, m.z);
    atomicAdd(d + 3, m.w);
#endif
}

// ---------------- kernel 1: zero accumulators ----------------
__global__ void k_zero() {
    int i = blockIdx.x * blockDim.x + threadIdx.x;
    int stride = gridDim.x * blockDim.x;
    float4 z = make_float4(0.f, 0.f, 0.f, 0.f);
    float4* a1 = (float4*)g_agg1;
    for (int j = i; j < NN * 4; j += stride) a1[j] = z;
    float4* a2 = (float4*)g_agg2;
    for (int j = i; j < NN * 3; j += stride) a2[j] = z;
    for (int j = i; j < NN; j += stride) g_deg[j] = 0.f;
}

// ---------------- kernel 2: node GEMM layer 1 ----------------
// Wc[i][o]: o<16 -> W1[0,i,o] ; o in 16..31 -> W1[1,i,o]-W1[0,i,o] ; o in 32..47 -> root1[i,o]
__global__ void k_gemm1(const float* __restrict__ x, const float* __restrict__ W1,
                        const float* __restrict__ root1) {
    __shared__ float Wc[32][64];
    int tid = threadIdx.x;
    // zero the pad columns 48..63
    for (int idx = tid; idx < 32 * 16; idx += blockDim.x)
        Wc[idx >> 4][48 + (idx & 15)] = 0.f;
    for (int idx = tid; idx < 32 * 48; idx += blockDim.x) {
        int i = idx / 48, o = idx % 48;
        float w;
        if (o < 16)      w = W1[i * 16 + o];
        else if (o < 32) w = W1[512 + i * 16 + (o - 16)] - W1[i * 16 + (o - 16)];
        else             w = root1[i * 16 + (o - 32)];
        Wc[i][o] = w;
    }
    __syncthreads();
    int lane = tid & 31, warp = tid >> 5;
    for (int n = blockIdx.x * 8 + warp; n < NN; n += gridDim.x * 8) {
        float xv = x[n * 32 + lane];
        float acc0 = 0.f, acc1 = 0.f;
#pragma unroll
        for (int i = 0; i < 32; i++) {
            float xi = __shfl_sync(0xffffffffu, xv, i);
            acc0 = fmaf(xi, Wc[i][lane], acc0);
            acc1 = fmaf(xi, Wc[i][lane + 32], acc1);
        }
        g_P1[n * 32 + lane] = acc0;
        if (lane < 16) g_R1[n * 16 + lane] = acc1;
    }
}

// ---------------- kernel 3: edge scatter layer 1 ----------------
// 4 lanes per edge; each lane handles a float4 slice of the 16 output channels.
// edge_index is int32 (JAX x64-disabled randint), laid out [2, E] row-major.
__global__ void k_edge1(const int* __restrict__ ei, const float* __restrict__ attr) {
    int t = blockIdx.x * blockDim.x + threadIdx.x;
    int e = t >> 2;
    int lane = t & 3;
    if (e >= EE) return;
    int src = ei[e];
    int dst = ei[EE + e];
    float v = attr[e];
    const float4* pa = (const float4*)&g_P1[src * 32];
    float4 a = pa[lane];
    float4 b = pa[4 + lane];
    float4 m;
    m.x = fmaf(v, b.x, a.x);
    m.y = fmaf(v, b.y, a.y);
    m.z = fmaf(v, b.z, a.z);
    m.w = fmaf(v, b.w, a.w);
    red_add_f4(&g_agg1[dst * 16 + lane * 4], m);
    if (lane == 0) atomicAdd(&g_deg[dst], 1.0f);
}

// ---------------- kernel 4: post layer1 (mean + root + bias + ELU) fused with node GEMM layer 2 ----------------
// Wc2[i][o]: o<12 -> W2[0,i,j] (j=o, pad j>=10 -> 0); o in 12..23 -> W2[1]-W2[0]; o in 24..35 -> root2; else 0
__global__ void k_post(const float* __restrict__ b1, const float* __restrict__ W2,
                       const float* __restrict__ root2) {
    __shared__ float Wc[16][64];
    __shared__ float b1s[16];
    int tid = threadIdx.x;
    if (tid < 16) b1s[tid] = b1[tid];
    for (int idx = tid; idx < 16 * 64; idx += blockDim.x) {
        int i = idx >> 6, o = idx & 63;
        float w = 0.f;
        if (o < 12)      { int j = o;      if (j < 10) w = W2[i * 10 + j]; }
        else if (o < 24) { int j = o - 12; if (j < 10) w = W2[160 + i * 10 + j] - W2[i * 10 + j]; }
        else if (o < 36) { int j = o - 24; if (j < 10) w = root2[i * 10 + j]; }
        Wc[i][o] = w;
    }
    __syncthreads();
    int lane = tid & 31, warp = tid >> 5;
    for (int n = blockIdx.x * 8 + warp; n < NN; n += gridDim.x * 8) {
        float h = 0.f;
        if (lane < 16) {
            float d = fmaxf(g_deg[n], 1.0f);
            float s = g_agg1[n * 16 + lane] / d + g_R1[n * 16 + lane] + b1s[lane];
            h = (s > 0.f) ? s : (expf(s) - 1.0f);   // ELU alpha=1
        }
        float acc0 = 0.f, acc1 = 0.f;
#pragma unroll
        for (int i = 0; i < 16; i++) {
            float hi = __shfl_sync(0xffffffffu, h, i);
            acc0 = fmaf(hi, Wc[i][lane], acc0);
            acc1 = fmaf(hi, Wc[i][lane + 32], acc1);
        }
        if (lane < 24) g_P2[n * 24 + lane] = acc0;
        else           g_R2[n * 12 + (lane - 24)] = acc0;   // R2 cols 0..7
        if (lane < 4)  g_R2[n * 12 + 8 + lane] = acc1;      // R2 cols 8..11 (10,11 are pad)
    }
}

// ---------------- kernel 5: edge scatter layer 2 ----------------
// 4 lanes per edge, lanes 0..2 active (12 padded channels).
__global__ void k_edge2(const int* __restrict__ ei, const float* __restrict__ attr) {
    int t = blockIdx.x * blockDim.x + threadIdx.x;
    int e = t >> 2;
    int lane = t & 3;
    if (e >= EE) return;
    if (lane >= 3) return;
    int src = ei[e];
    int dst = ei[EE + e];
    float v = attr[e];
    float4 a = *(const float4*)&g_P2[src * 24 + lane * 4];
    float4 b = *(const float4*)&g_P2[src * 24 + 12 + lane * 4];
    float4 m;
    m.x = fmaf(v, b.x, a.x);
    m.y = fmaf(v, b.y, a.y);
    m.z = fmaf(v, b.z, a.z);
    m.w = fmaf(v, b.w, a.w);
    red_add_f4(&g_agg2[dst * 12 + lane * 4], m);
}

// ---------------- kernel 6: mean + root + bias + log_softmax ----------------
__global__ void k_final(const float* __restrict__ b2, float* __restrict__ out) {
    int lane = threadIdx.x & 31, warp = threadIdx.x >> 5;
    for (int n = blockIdx.x * 8 + warp; n < NN; n += gridDim.x * 8) {
        float val = -INFINITY;
        if (lane < 10) {
            float d = fmaxf(g_deg[n], 1.0f);
            val = g_agg2[n * 12 + lane] / d + g_R2[n * 12 + lane] + b2[lane];
        }
        float m = val;
#pragma unroll
        for (int off = 16; off >= 1; off >>= 1)
            m = fmaxf(m, __shfl_xor_sync(0xffffffffu, m, off));
        float ex = (lane < 10) ? expf(val - m) : 0.f;
        float s = ex;
#pragma unroll
        for (int off = 16; off >= 1; off >>= 1)
            s += __shfl_xor_sync(0xffffffffu, s, off);
        if (lane < 10) out[n * 10 + lane] = val - m - logf(s);
    }
}

extern "C" void kernel_launch(void* const* d_in, const int* in_sizes, int n_in,
                              void* d_out, int out_size) {
    const float* x     = (const float*)d_in[0];
    const int*   ei    = (const int*)d_in[1];    // int32: JAX x64-disabled randint
    const float* attr  = (const float*)d_in[2];
    const float* W1    = (const float*)d_in[3];
    const float* root1 = (const float*)d_in[4];
    const float* b1    = (const float*)d_in[5];
    const float* W2    = (const float*)d_in[6];
    const float* root2 = (const float*)d_in[7];
    const float* b2    = (const float*)d_in[8];
    float* out = (float*)d_out;

    k_zero<<<512, 256>>>();
    k_gemm1<<<(NN + 7) / 8, 256>>>(x, W1, root1);
    k_edge1<<<(EE * 4 + 255) / 256, 256>>>(ei, attr);
    k_post<<<(NN + 7) / 8, 256>>>(b1, W2, root2);
    k_edge2<<<(EE * 4 + 255) / 256, 256>>>(ei, attr);
    k_final<<<(NN + 7) / 8, 256>>>(b2, out);
}

// round 7
// speedup vs baseline: 1.7335x; 1.7335x over previous
#include <cuda_runtime.h>
#include <cuda_bf16.h>
#include <math.h>

// Problem constants (fixed by the reference)
#define NN 100000
#define EE 1600000

// ---------------- scratch (no allocation allowed -> __device__ globals) ----------------
// P1[n][0..15]  = (x @ W0)[n]      (A)
// P1[n][16..31] = (x @ (W1-W0))[n] (B)
__device__ __align__(16) float g_P1[NN * 32];       // 12.8 MB
__device__ __align__(16) float g_R1[NN * 16];       //  6.4 MB  x @ root1
__device__ __align__(16) float g_agg1[NN * 16];     //  6.4 MB
__device__ __align__(16) float g_deg[NN];           //  0.4 MB
// P2[n][0..11] = (h @ W0_2) padded 10->12, P2[n][12..23] = (h @ (W1_2-W0_2)) padded
__device__ __align__(16) float g_P2[NN * 24];       //  9.6 MB
__device__ __align__(16) float g_R2[NN * 12];       //  4.8 MB  h @ root2 padded 10->12
__device__ __align__(16) float g_agg2[NN * 12];     //  4.8 MB

__device__ __forceinline__ void red_add_f4(float* d, float4 m) {
#if defined(__CUDA_ARCH__) && (__CUDA_ARCH__ >= 900) && (CUDART_VERSION >= 12080)
    atomicAdd(reinterpret_cast<float4*>(d), m);
#else
    atomicAdd(d + 0, m.x);
    atomicAdd(d + 1, m.y);
    atomicAdd(d + 2, m.z);
    atomicAdd(d + 3, m.w);
#endif
}

// ---------------- kernel 1: node GEMM layer 1 (thread-per-node) + zero agg1/deg ----------------
// Wc[i][o], i<32, o<48: o<16 -> W1[0,i,o]; o in 16..31 -> W1[1]-W1[0]; o in 32..47 -> root1
__global__ void __launch_bounds__(256) k_gemm1(const float* __restrict__ x,
                                               const float* __restrict__ W1,
                                               const float* __restrict__ root1) {
    __shared__ float Wc[32 * 48];
    int tid = threadIdx.x;
    for (int idx = tid; idx < 32 * 48; idx += 256) {
        int i = idx / 48, o = idx % 48;
        float w;
        if (o < 16)      w = W1[i * 16 + o];
        else if (o < 32) w = W1[512 + i * 16 + (o - 16)] - W1[i * 16 + (o - 16)];
        else             w = root1[i * 16 + (o - 32)];
        Wc[idx] = w;
    }
    // zero agg1 + deg (grid-stride across whole grid)
    {
        int gt = blockIdx.x * 256 + tid, gs = gridDim.x * 256;
        float4 z = make_float4(0.f, 0.f, 0.f, 0.f);
        float4* a1 = (float4*)g_agg1;
        for (int j = gt; j < NN * 4; j += gs) a1[j] = z;
        for (int j = gt; j < NN; j += gs) g_deg[j] = 0.f;
    }
    __syncthreads();

    int n = blockIdx.x * 256 + tid;
    if (n >= NN) return;

    float xr[32];
    const float4* xp = (const float4*)(x + n * 32);
#pragma unroll
    for (int q = 0; q < 8; q++) {
        float4 t4 = xp[q];
        xr[q * 4 + 0] = t4.x; xr[q * 4 + 1] = t4.y;
        xr[q * 4 + 2] = t4.z; xr[q * 4 + 3] = t4.w;
    }

    float4* p1 = (float4*)(g_P1 + n * 32);
    float4* r1 = (float4*)(g_R1 + n * 16);

#pragma unroll
    for (int half = 0; half < 2; half++) {
        float acc[24];
#pragma unroll
        for (int o = 0; o < 24; o++) acc[o] = 0.f;
#pragma unroll
        for (int i = 0; i < 32; i++) {
            const float4* w4 = (const float4*)&Wc[i * 48 + half * 24];
            float xi = xr[i];
#pragma unroll
            for (int q = 0; q < 6; q++) {
                float4 w = w4[q];
                acc[q * 4 + 0] = fmaf(xi, w.x, acc[q * 4 + 0]);
                acc[q * 4 + 1] = fmaf(xi, w.y, acc[q * 4 + 1]);
                acc[q * 4 + 2] = fmaf(xi, w.z, acc[q * 4 + 2]);
                acc[q * 4 + 3] = fmaf(xi, w.w, acc[q * 4 + 3]);
            }
        }
        if (half == 0) {
            // outputs 0..23 -> P1 cols 0..23
#pragma unroll
            for (int q = 0; q < 6; q++)
                p1[q] = make_float4(acc[q * 4], acc[q * 4 + 1], acc[q * 4 + 2], acc[q * 4 + 3]);
        } else {
            // outputs 24..47: 24..31 -> P1 cols 24..31, 32..47 -> R1 cols 0..15
            p1[6] = make_float4(acc[0], acc[1], acc[2], acc[3]);
            p1[7] = make_float4(acc[4], acc[5], acc[6], acc[7]);
#pragma unroll
            for (int q = 0; q < 4; q++)
                r1[q] = make_float4(acc[8 + q * 4], acc[9 + q * 4], acc[10 + q * 4], acc[11 + q * 4]);
        }
    }
}

// ---------------- kernel 2: edge scatter layer 1 ----------------
// 4 lanes per edge; each lane handles a float4 slice of the 16 output channels.
__global__ void k_edge1(const int* __restrict__ ei, const float* __restrict__ attr) {
    int t = blockIdx.x * blockDim.x + threadIdx.x;
    int e = t >> 2;
    int lane = t & 3;
    if (e >= EE) return;
    int src = ei[e];
    int dst = ei[EE + e];
    float v = attr[e];
    const float4* pa = (const float4*)&g_P1[src * 32];
    float4 a = pa[lane];
    float4 b = pa[4 + lane];
    float4 m;
    m.x = fmaf(v, b.x, a.x);
    m.y = fmaf(v, b.y, a.y);
    m.z = fmaf(v, b.z, a.z);
    m.w = fmaf(v, b.w, a.w);
    red_add_f4(&g_agg1[dst * 16 + lane * 4], m);
    if (lane == 0) atomicAdd(&g_deg[dst], 1.0f);
}

// ---------------- kernel 3: post layer1 (mean + root + bias + ELU) fused with node GEMM layer 2 ----------------
// thread-per-node; also zeroes agg2.
// Wc[i][o], i<16, o<36: o<12 -> W2[0,i,j] (j=o, pad>=10 -> 0); 12..23 -> W2[1]-W2[0]; 24..35 -> root2
__global__ void __launch_bounds__(256) k_post(const float* __restrict__ b1,
                                              const float* __restrict__ W2,
                                              const float* __restrict__ root2) {
    __shared__ float Wc[16 * 36];
    __shared__ float b1s[16];
    int tid = threadIdx.x;
    if (tid < 16) b1s[tid] = b1[tid];
    for (int idx = tid; idx < 16 * 36; idx += 256) {
        int i = idx / 36, o = idx % 36;
        float w = 0.f;
        if (o < 12)      { int j = o;      if (j < 10) w = W2[i * 10 + j]; }
        else if (o < 24) { int j = o - 12; if (j < 10) w = W2[160 + i * 10 + j] - W2[i * 10 + j]; }
        else             { int j = o - 24; if (j < 10) w = root2[i * 10 + j]; }
        Wc[idx] = w;
    }
    // zero agg2
    {
        int gt = blockIdx.x * 256 + tid, gs = gridDim.x * 256;
        float4 z = make_float4(0.f, 0.f, 0.f, 0.f);
        float4* a2 = (float4*)g_agg2;
        for (int j = gt; j < NN * 3; j += gs) a2[j] = z;
    }
    __syncthreads();

    int n = blockIdx.x * 256 + tid;
    if (n >= NN) return;

    float inv = 1.0f / fmaxf(g_deg[n], 1.0f);
    const float4* ag = (const float4*)(g_agg1 + n * 16);
    const float4* rr = (const float4*)(g_R1 + n * 16);
    float h[16];
#pragma unroll
    for (int q = 0; q < 4; q++) {
        float4 a = ag[q];
        float4 r = rr[q];
        float s0 = fmaf(a.x, inv, r.x) + b1s[q * 4 + 0];
        float s1 = fmaf(a.y, inv, r.y) + b1s[q * 4 + 1];
        float s2 = fmaf(a.z, inv, r.z) + b1s[q * 4 + 2];
        float s3 = fmaf(a.w, inv, r.w) + b1s[q * 4 + 3];
        h[q * 4 + 0] = (s0 > 0.f) ? s0 : (__expf(s0) - 1.0f);
        h[q * 4 + 1] = (s1 > 0.f) ? s1 : (__expf(s1) - 1.0f);
        h[q * 4 + 2] = (s2 > 0.f) ? s2 : (__expf(s2) - 1.0f);
        h[q * 4 + 3] = (s3 > 0.f) ? s3 : (__expf(s3) - 1.0f);
    }

    float acc[36];
#pragma unroll
    for (int o = 0; o < 36; o++) acc[o] = 0.f;
#pragma unroll
    for (int i = 0; i < 16; i++) {
        const float4* w4 = (const float4*)&Wc[i * 36];
        float hi = h[i];
#pragma unroll
        for (int q = 0; q < 9; q++) {
            float4 w = w4[q];
            acc[q * 4 + 0] = fmaf(hi, w.x, acc[q * 4 + 0]);
            acc[q * 4 + 1] = fmaf(hi, w.y, acc[q * 4 + 1]);
            acc[q * 4 + 2] = fmaf(hi, w.z, acc[q * 4 + 2]);
            acc[q * 4 + 3] = fmaf(hi, w.w, acc[q * 4 + 3]);
        }
    }

    float4* p2 = (float4*)(g_P2 + n * 24);
#pragma unroll
    for (int q = 0; q < 6; q++)
        p2[q] = make_float4(acc[q * 4], acc[q * 4 + 1], acc[q * 4 + 2], acc[q * 4 + 3]);
    float4* r2 = (float4*)(g_R2 + n * 12);
#pragma unroll
    for (int q = 0; q < 3; q++)
        r2[q] = make_float4(acc[24 + q * 4], acc[25 + q * 4], acc[26 + q * 4], acc[27 + q * 4]);
}

// ---------------- kernel 4: edge scatter layer 2 ----------------
// 4 lanes per edge, lanes 0..2 active (12 padded channels).
__global__ void k_edge2(const int* __restrict__ ei, const float* __restrict__ attr) {
    int t = blockIdx.x * blockDim.x + threadIdx.x;
    int e = t >> 2;
    int lane = t & 3;
    if (e >= EE) return;
    if (lane >= 3) return;
    int src = ei[e];
    int dst = ei[EE + e];
    float v = attr[e];
    float4 a = *(const float4*)&g_P2[src * 24 + lane * 4];
    float4 b = *(const float4*)&g_P2[src * 24 + 12 + lane * 4];
    float4 m;
    m.x = fmaf(v, b.x, a.x);
    m.y = fmaf(v, b.y, a.y);
    m.z = fmaf(v, b.z, a.z);
    m.w = fmaf(v, b.w, a.w);
    red_add_f4(&g_agg2[dst * 12 + lane * 4], m);
}

// ---------------- kernel 5: mean + root + bias + log_softmax (thread-per-node) ----------------
__global__ void __launch_bounds__(256) k_final(const float* __restrict__ b2,
                                               float* __restrict__ out) {
    __shared__ float b2s[12];
    int tid = threadIdx.x;
    if (tid < 12) b2s[tid] = (tid < 10) ? b2[tid] : 0.f;
    __syncthreads();
    int n = blockIdx.x * 256 + tid;
    if (n >= NN) return;

    float inv = 1.0f / fmaxf(g_deg[n], 1.0f);
    const float4* ag = (const float4*)(g_agg2 + n * 12);
    const float4* rr = (const float4*)(g_R2 + n * 12);
    float v[12];
#pragma unroll
    for (int q = 0; q < 3; q++) {
        float4 a = ag[q];
        float4 r = rr[q];
        v[q * 4 + 0] = fmaf(a.x, inv, r.x) + b2s[q * 4 + 0];
        v[q * 4 + 1] = fmaf(a.y, inv, r.y) + b2s[q * 4 + 1];
        v[q * 4 + 2] = fmaf(a.z, inv, r.z) + b2s[q * 4 + 2];
        v[q * 4 + 3] = fmaf(a.w, inv, r.w) + b2s[q * 4 + 3];
    }
    float m = v[0];
#pragma unroll
    for (int c = 1; c < 10; c++) m = fmaxf(m, v[c]);
    float s = 0.f;
#pragma unroll
    for (int c = 0; c < 10; c++) s += __expf(v[c] - m);
    float l = m + __logf(s);
    float2* o2 = (float2*)(out + n * 10);
#pragma unroll
    for (int q = 0; q < 5; q++)
        o2[q] = make_float2(v[q * 2] - l, v[q * 2 + 1] - l);
}

extern "C" void kernel_launch(void* const* d_in, const int* in_sizes, int n_in,
                              void* d_out, int out_size) {
    const float* x     = (const float*)d_in[0];
    const int*   ei    = (const int*)d_in[1];    // int32 (JAX x64-disabled randint)
    const float* attr  = (const float*)d_in[2];
    const float* W1    = (const float*)d_in[3];
    const float* root1 = (const float*)d_in[4];
    const float* b1    = (const float*)d_in[5];
    const float* W2    = (const float*)d_in[6];
    const float* root2 = (const float*)d_in[7];
    const float* b2    = (const float*)d_in[8];
    float* out = (float*)d_out;

    const int NBLK = (NN + 255) / 256;
    k_gemm1<<<NBLK, 256>>>(x, W1, root1);
    k_edge1<<<(EE * 4 + 255) / 256, 256>>>(ei, attr);
    k_post<<<NBLK, 256>>>(b1, W2, root2);
    k_edge2<<<(EE * 4 + 255) / 256, 256>>>(ei, attr);
    k_final<<<NBLK, 256>>>(b2, out);
}